// round 9
// baseline (speedup 1.0000x reference)
#include <cuda_runtime.h>

#define H     51
#define G     204
#define BB    8
#define TPB   768
#define NCTA  128
#define T_IN  512
#define T_FUT 64
#define T_TOT 576
#define NTICK 514

typedef unsigned long long ull;

struct __align__(16) Smem {
    float2 W1[H + 1][102];   // k=0: W_ih1; k=1..51: W_hh1 col k-1; pair (ga,gb)
    float2 W2[2 * H][102];   // k=0..50: W_ih2 col k; 51..101: W_hh2 col k-51
    float2 W3[2 * H][102];
    float2 bp[3][102];
    float  wlin[52];
    float  blin;
    float  padA[3];
    float  hcat[154][BB];    // row 0 = x; 1..51 h1; 52..102 h2; 103..153 h3
    float  c[3 * H][BB];     // c-state parking for the future phase
};

__device__ __forceinline__ ull pack2(float x) {
    ull r; asm("mov.b64 %0, {%1, %1};" : "=l"(r) : "f"(x)); return r;
}
__device__ __forceinline__ void unpack2(ull v, float &a, float &b) {
    asm("mov.b64 {%0, %1}, %2;" : "=f"(a), "=f"(b) : "l"(v));
}
__device__ __forceinline__ ull fma2(ull a, ull b, ull c) {
    ull d; asm("fma.rn.f32x2 %0, %1, %2, %3;" : "=l"(d) : "l"(a), "l"(b), "l"(c)); return d;
}
__device__ __forceinline__ ull add2(ull a, ull b) {
    ull d; asm("add.rn.f32x2 %0, %1, %2;" : "=l"(d) : "l"(a), "l"(b)); return d;
}
__device__ __forceinline__ float sigf(float x) {
    return __fdividef(1.0f, 1.0f + __expf(-x));
}
__device__ __forceinline__ float tanh_(float x) {
    return 1.0f - __fdividef(2.0f, __expf(2.0f * x) + 1.0f);
}

__device__ __forceinline__ void mac8(ull acc[8], float2 w, const float *row) {
    ulonglong2 va = *(const ulonglong2 *)row;
    ulonglong2 vb = *(const ulonglong2 *)(row + 4);
    ull wx = pack2(w.x), wy = pack2(w.y);
    acc[0] = fma2(wx, va.x, acc[0]); acc[1] = fma2(wx, va.y, acc[1]);
    acc[2] = fma2(wx, vb.x, acc[2]); acc[3] = fma2(wx, vb.y, acc[3]);
    acc[4] = fma2(wy, va.x, acc[4]); acc[5] = fma2(wy, va.y, acc[5]);
    acc[6] = fma2(wy, vb.x, acc[6]); acc[7] = fma2(wy, vb.y, acc[7]);
}

// 2 batch elems: thread slice q = sel*2 + khalf; sel picks (i,g) vs (f,o) locality
__device__ __forceinline__ void cell2(const ull acc[8], const ull prt[8],
                                      int sel, int q, float creg[2], float hn[2]) {
    ull iu = sel ? prt[q]     : acc[q];
    ull gu = sel ? prt[4 + q] : acc[4 + q];
    ull fu = sel ? acc[q]     : prt[q];
    ull ou = sel ? acc[4 + q] : prt[4 + q];
    float i0, i1, g0, g1, f0, f1, o0, o1;
    unpack2(iu, i0, i1); unpack2(gu, g0, g1);
    unpack2(fu, f0, f1); unpack2(ou, o0, o1);
    float cn0 = sigf(f0) * creg[0] + sigf(i0) * tanh_(g0);
    float cn1 = sigf(f1) * creg[1] + sigf(i1) * tanh_(g1);
    hn[0] = sigf(o0) * tanh_(cn0);
    hn[1] = sigf(o1) * tanh_(cn1);
    creg[0] = cn0; creg[1] = cn1;
}

// 4 batch elems (future loop); sel picks which packed halves are local
__device__ __forceinline__ void cell4(const ull acc[8], const ull prt[8], int sel,
                                      float creg[4], float hn[4]) {
    ull iv0, iv1, gv0, gv1, fv0, fv1, ov0, ov1;
    if (sel == 0) {
        iv0 = acc[0]; iv1 = acc[1]; gv0 = acc[4]; gv1 = acc[5];
        fv0 = prt[0]; fv1 = prt[1]; ov0 = prt[4]; ov1 = prt[5];
    } else {
        iv0 = prt[2]; iv1 = prt[3]; gv0 = prt[6]; gv1 = prt[7];
        fv0 = acc[2]; fv1 = acc[3]; ov0 = acc[6]; ov1 = acc[7];
    }
    float ig[4], fg[4], gg[4], og[4];
    unpack2(iv0, ig[0], ig[1]); unpack2(iv1, ig[2], ig[3]);
    unpack2(fv0, fg[0], fg[1]); unpack2(fv1, fg[2], fg[3]);
    unpack2(gv0, gg[0], gg[1]); unpack2(gv1, gg[2], gg[3]);
    unpack2(ov0, og[0], og[1]); unpack2(ov1, og[2], og[3]);
#pragma unroll
    for (int u = 0; u < 4; u++) {
        float cn = sigf(fg[u]) * creg[u] + sigf(ig[u]) * tanh_(gg[u]);
        hn[u]    = sigf(og[u]) * tanh_(cn);
        creg[u]  = cn;
    }
}

__device__ __forceinline__ float head_dot(const Smem *s, int b) {
    float sum = s->blin;
#pragma unroll 3
    for (int j = 0; j < H; j++) sum = fmaf(s->wlin[j], s->hcat[103 + j][b], sum);
    return sum;
}

__global__ void __launch_bounds__(TPB, 1)
lstm_seq_kernel(const float *__restrict__ input,
                const float *__restrict__ W_ih1, const float *__restrict__ W_hh1,
                const float *__restrict__ b_ih1, const float *__restrict__ b_hh1,
                const float *__restrict__ W_ih2, const float *__restrict__ W_hh2,
                const float *__restrict__ b_ih2, const float *__restrict__ b_hh2,
                const float *__restrict__ W_ih3, const float *__restrict__ W_hh3,
                const float *__restrict__ b_ih3, const float *__restrict__ b_hh3,
                const float *__restrict__ W_lin, const float *__restrict__ b_lin,
                float *__restrict__ out) {
    extern __shared__ char raw[];
    Smem *s = (Smem *)raw;

    const int tid = threadIdx.x;
    const int b0  = blockIdx.x * BB;
    const int L   = tid >> 8;        // layer block of 256 lanes
    const int l   = tid & 255;
    const bool gate_lane = (l < 204);
    const int  p     = gate_lane ? (l >> 1) : 101;   // gate pair 0..101
    const int  khalf = l & 1;                        // k-half
    const int  j     = p >> 1;
    const int  sel   = p & 1;
    const int  q     = sel * 2 + khalf;              // batch slice (2 elems)
    const bool head_lane = (L == 0) && (l >= 204) && (l < 204 + BB);
    const bool xf_lane   = (L == 1) && (l >= 204) && (l < 204 + BB);

    // ---- one-time staging (pair (ga,gb) = (j+sel*51, j+sel*51+102)) ----
    for (int idx = tid; idx < (H + 1) * 102; idx += TPB) {
        int k = idx / 102, l2 = idx % 102;
        int ga = (l2 >> 1) + (l2 & 1) * 51, gb = ga + 102;
        float2 v;
        if (k == 0) v = make_float2(W_ih1[ga], W_ih1[gb]);
        else        v = make_float2(W_hh1[ga * H + k - 1], W_hh1[gb * H + k - 1]);
        s->W1[k][l2] = v;
    }
    for (int idx = tid; idx < 2 * H * 102; idx += TPB) {
        int k = idx / 102, l2 = idx % 102;
        int ga = (l2 >> 1) + (l2 & 1) * 51, gb = ga + 102;
        int kk = (k < H) ? k : k - H;
        const float *s2 = (k < H) ? W_ih2 : W_hh2;
        const float *s3 = (k < H) ? W_ih3 : W_hh3;
        s->W2[k][l2] = make_float2(s2[ga * H + kk], s2[gb * H + kk]);
        s->W3[k][l2] = make_float2(s3[ga * H + kk], s3[gb * H + kk]);
    }
    for (int idx = tid; idx < 3 * 102; idx += TPB) {
        int ly = idx / 102, l2 = idx % 102;
        int ga = (l2 >> 1) + (l2 & 1) * 51, gb = ga + 102;
        const float *bi = (ly == 0) ? b_ih1 : (ly == 1) ? b_ih2 : b_ih3;
        const float *bh = (ly == 0) ? b_hh1 : (ly == 1) ? b_hh2 : b_hh3;
        s->bp[ly][l2] = make_float2(bi[ga] + bh[ga], bi[gb] + bh[gb]);
    }
    if (tid < H) s->wlin[tid] = W_lin[tid];
    if (tid == 0) s->blin = b_lin[0];
    for (int idx = tid; idx < 153 * BB; idx += TPB) (&s->hcat[1][0])[idx] = 0.0f;
    if (tid < BB) s->hcat[0][tid] = input[(size_t)(b0 + tid) * T_IN];  // x(0)
    __syncthreads();

    float creg[2] = {0.f, 0.f};

    // ===== pipelined main loop: tick t -> L1@t, L2@t-1, L3@t-2 =====
    for (int t = 0; t < NTICK; t++) {
        ull   acc[8] = {};
        float xr = 0.0f;
        if (gate_lane) {
            if (khalf == 0) {
                float2 bv = s->bp[L][p];
                ull bx = pack2(bv.x), by = pack2(bv.y);
#pragma unroll
                for (int i = 0; i < 4; i++) { acc[i] = bx; acc[4 + i] = by; }
            }
            if (L == 0) {
                const int k0 = khalf * 26, k1 = k0 + 26;   // K=52 rows [x|h1]
#pragma unroll 2
                for (int k = k0; k < k1; k++) mac8(acc, s->W1[k][p], &s->hcat[k][0]);
            } else if (L == 1) {
                const int k0 = khalf * 51, k1 = k0 + 51;   // rows [h1|h2]
#pragma unroll 3
                for (int k = k0; k < k1; k++) mac8(acc, s->W2[k][p], &s->hcat[1 + k][0]);
            } else {
                const int k0 = khalf * 51, k1 = k0 + 51;   // rows [h2|h3]
#pragma unroll 3
                for (int k = k0; k < k1; k++) mac8(acc, s->W3[k][p], &s->hcat[52 + k][0]);
            }
        } else if (head_lane && t >= 3) {
            int b = l - 204;
            out[(size_t)(b0 + b) * T_TOT + (t - 3)] = head_dot(s, b);
        } else if (xf_lane && t + 1 < T_IN) {
            xr = input[(size_t)(b0 + l - 204) * T_IN + t + 1];
        }
        // combine k-halves, then exchange with gate-pair partner
        ull prt[8];
#pragma unroll
        for (int i = 0; i < 8; i++)
            acc[i] = add2(acc[i], __shfl_xor_sync(0xffffffffu, acc[i], 1));
#pragma unroll
        for (int i = 0; i < 8; i++)
            prt[i] = __shfl_xor_sync(0xffffffffu, acc[i], 2);

        const bool valid = gate_lane &&
            ((L == 0) ? (t <= T_IN - 1)
                      : (L == 1) ? (t >= 1 && t <= T_IN) : (t >= 2));
        float hn[2];
        if (valid) cell2(acc, prt, sel, q, creg, hn);
        __syncthreads();
        if (valid) *(float2 *)&s->hcat[1 + L * H + j][2 * q] = make_float2(hn[0], hn[1]);
        if (xf_lane && t + 1 < T_IN) s->hcat[0][l - 204] = xr;
        __syncthreads();
    }

    // ---- drain: park c-state, out(511), first autoregressive input ----
    if (gate_lane) *(float2 *)&s->c[L * H + j][2 * q] = make_float2(creg[0], creg[1]);
    if (tid < BB) {
        float v = head_dot(s, tid);
        out[(size_t)(b0 + tid) * T_TOT + (T_IN - 1)] = v;
        s->hcat[0][tid] = v;
    }
    __syncthreads();

    // ===== autoregressive future: wide lanes, k-thirds in adjacent lanes =====
    const int  m    = tid & 31, w5 = tid >> 5;
    const int  fpr  = w5 * 10 + m / 3;
    const int  fq   = m % 3;
    const bool fact = (tid < 384) && (m < 30) && (fpr < 102);
    const int  fp   = fact ? fpr : 101;
    const int  fj   = fp >> 1, fsel = fp & 1;
    const int  psrc = (3 * ((fp ^ 1) - w5 * 10)) & 31;

    for (int fs = 0; fs < T_FUT; fs++) {
#pragma unroll
        for (int lay = 0; lay < 3; lay++) {
            const float2(*W)[102];
            const float(*V)[BB];
            int k0, k1;
            if (lay == 0)      { W = s->W1; V = s->hcat;
                                 k0 = (fq == 0) ? 0 : (fq == 1) ? 18 : 35;
                                 k1 = (fq == 0) ? 18 : (fq == 1) ? 35 : 52; }
            else if (lay == 1) { W = s->W2; V = s->hcat + 1;  k0 = fq * 34; k1 = k0 + 34; }
            else               { W = s->W3; V = s->hcat + 52; k0 = fq * 34; k1 = k0 + 34; }
            ull acc[8] = {};
            if (fact) {
                if (fq == 0) {
                    float2 bv = s->bp[lay][fp];
                    ull bx = pack2(bv.x), by = pack2(bv.y);
#pragma unroll
                    for (int i = 0; i < 4; i++) { acc[i] = bx; acc[4 + i] = by; }
                }
#pragma unroll 2
                for (int k = k0; k < k1; k++) mac8(acc, W[k][fp], &V[k][0]);
            }
            ull prt[8];
#pragma unroll
            for (int i = 0; i < 8; i++) {
                ull t1 = __shfl_down_sync(0xffffffffu, acc[i], 1);
                ull t2 = __shfl_down_sync(0xffffffffu, acc[i], 2);
                acc[i] = add2(add2(acc[i], t1), t2);
            }
#pragma unroll
            for (int i = 0; i < 8; i++)
                prt[i] = __shfl_sync(0xffffffffu, acc[i], psrc);
            __syncthreads();
            if (fact && fq == 0) {
                float4 cv = *(float4 *)&s->c[lay * H + fj][fsel * 4];
                float cr[4] = {cv.x, cv.y, cv.z, cv.w};
                float hn[4];
                cell4(acc, prt, fsel, cr, hn);
                *(float4 *)&s->c[lay * H + fj][fsel * 4] =
                    make_float4(cr[0], cr[1], cr[2], cr[3]);
                *(float4 *)&s->hcat[1 + lay * H + fj][fsel * 4] =
                    make_float4(hn[0], hn[1], hn[2], hn[3]);
            }
            __syncthreads();
        }
        if (tid < BB) {
            float v = head_dot(s, tid);
            out[(size_t)(b0 + tid) * T_TOT + T_IN + fs] = v;
            s->hcat[0][tid] = v;
        }
        __syncthreads();
    }
}

extern "C" void kernel_launch(void *const *d_in, const int *in_sizes, int n_in,
                              void *d_out, int out_size) {
    (void)in_sizes; (void)n_in; (void)out_size;
    cudaFuncSetAttribute(lstm_seq_kernel,
                         cudaFuncAttributeMaxDynamicSharedMemorySize,
                         (int)sizeof(Smem));
    lstm_seq_kernel<<<NCTA, TPB, sizeof(Smem)>>>(
        (const float *)d_in[0],
        (const float *)d_in[1], (const float *)d_in[2],
        (const float *)d_in[3], (const float *)d_in[4],
        (const float *)d_in[5], (const float *)d_in[6],
        (const float *)d_in[7], (const float *)d_in[8],
        (const float *)d_in[9], (const float *)d_in[10],
        (const float *)d_in[11], (const float *)d_in[12],
        (const float *)d_in[13], (const float *)d_in[14],
        (float *)d_out);
}

// round 10
// speedup vs baseline: 1.2565x; 1.2565x over previous
#include <cuda_runtime.h>

#define H     51
#define G     204
#define BB    8
#define TPB   768
#define NCTA  128
#define T_IN  512
#define T_FUT 64
#define T_TOT 576
#define NTICK 514

typedef unsigned long long ull;

struct __align__(16) Smem {
    float2 W1[H + 1][102];   // k=0: W_ih1; k=1..51: W_hh1 col k-1; pair (ga,gb)
    float2 W2[2 * H][102];   // k=0..50: W_ih2 col k; 51..101: W_hh2 col k-51
    float2 W3[2 * H][102];
    float2 bp[3][102];
    float  wlin[52];
    float  blin;
    float  padA[3];
    float  hcat[154][BB];    // row 0 = x; 1..51 h1; 52..102 h2; 103..153 h3
    float  c[3 * H][BB];     // c-state parking for the future phase
};

__device__ __forceinline__ ull pack2(float x) {
    ull r; asm("mov.b64 %0, {%1, %1};" : "=l"(r) : "f"(x)); return r;
}
__device__ __forceinline__ void unpack2(ull v, float &a, float &b) {
    asm("mov.b64 {%0, %1}, %2;" : "=f"(a), "=f"(b) : "l"(v));
}
__device__ __forceinline__ ull fma2(ull a, ull b, ull c) {
    ull d; asm("fma.rn.f32x2 %0, %1, %2, %3;" : "=l"(d) : "l"(a), "l"(b), "l"(c)); return d;
}
__device__ __forceinline__ ull add2(ull a, ull b) {
    ull d; asm("add.rn.f32x2 %0, %1, %2;" : "=l"(d) : "l"(a), "l"(b)); return d;
}
__device__ __forceinline__ float sigf(float x) {
    return __fdividef(1.0f, 1.0f + __expf(-x));
}
__device__ __forceinline__ float tanh_(float x) {
    return 1.0f - __fdividef(2.0f, __expf(2.0f * x) + 1.0f);
}

__device__ __forceinline__ void mac8(ull acc[8], float2 w, const float *row) {
    ulonglong2 va = *(const ulonglong2 *)row;
    ulonglong2 vb = *(const ulonglong2 *)(row + 4);
    ull wx = pack2(w.x), wy = pack2(w.y);
    acc[0] = fma2(wx, va.x, acc[0]); acc[1] = fma2(wx, va.y, acc[1]);
    acc[2] = fma2(wx, vb.x, acc[2]); acc[3] = fma2(wx, vb.y, acc[3]);
    acc[4] = fma2(wy, va.x, acc[4]); acc[5] = fma2(wy, va.y, acc[5]);
    acc[6] = fma2(wy, vb.x, acc[6]); acc[7] = fma2(wy, vb.y, acc[7]);
}

// 2 batch elems; ALL register-array indices compile-time (no local-mem demotion)
__device__ __forceinline__ void cell2(const ull acc[8], const ull prt[8],
                                      int sel, int khalf, float creg[2], float hn[2]) {
    ull iu, gu, fu, ou;
    if (sel == 0) {
        if (khalf == 0) { iu = acc[0]; gu = acc[4]; fu = prt[0]; ou = prt[4]; }
        else            { iu = acc[1]; gu = acc[5]; fu = prt[1]; ou = prt[5]; }
    } else {
        if (khalf == 0) { iu = prt[2]; gu = prt[6]; fu = acc[2]; ou = acc[6]; }
        else            { iu = prt[3]; gu = prt[7]; fu = acc[3]; ou = acc[7]; }
    }
    float i0, i1, g0, g1, f0, f1, o0, o1;
    unpack2(iu, i0, i1); unpack2(gu, g0, g1);
    unpack2(fu, f0, f1); unpack2(ou, o0, o1);
    float cn0 = sigf(f0) * creg[0] + sigf(i0) * tanh_(g0);
    float cn1 = sigf(f1) * creg[1] + sigf(i1) * tanh_(g1);
    hn[0] = sigf(o0) * tanh_(cn0);
    hn[1] = sigf(o1) * tanh_(cn1);
    creg[0] = cn0; creg[1] = cn1;
}

// 4 batch elems (future loop); sel branch keeps indices compile-time
__device__ __forceinline__ void cell4(const ull acc[8], const ull prt[8], int sel,
                                      float creg[4], float hn[4]) {
    ull iv0, iv1, gv0, gv1, fv0, fv1, ov0, ov1;
    if (sel == 0) {
        iv0 = acc[0]; iv1 = acc[1]; gv0 = acc[4]; gv1 = acc[5];
        fv0 = prt[0]; fv1 = prt[1]; ov0 = prt[4]; ov1 = prt[5];
    } else {
        iv0 = prt[2]; iv1 = prt[3]; gv0 = prt[6]; gv1 = prt[7];
        fv0 = acc[2]; fv1 = acc[3]; ov0 = acc[6]; ov1 = acc[7];
    }
    float ig[4], fg[4], gg[4], og[4];
    unpack2(iv0, ig[0], ig[1]); unpack2(iv1, ig[2], ig[3]);
    unpack2(fv0, fg[0], fg[1]); unpack2(fv1, fg[2], fg[3]);
    unpack2(gv0, gg[0], gg[1]); unpack2(gv1, gg[2], gg[3]);
    unpack2(ov0, og[0], og[1]); unpack2(ov1, og[2], og[3]);
#pragma unroll
    for (int u = 0; u < 4; u++) {
        float cn = sigf(fg[u]) * creg[u] + sigf(ig[u]) * tanh_(gg[u]);
        hn[u]    = sigf(og[u]) * tanh_(cn);
        creg[u]  = cn;
    }
}

__device__ __forceinline__ float head_dot(const Smem *s, int b) {
    float sum = s->blin;
#pragma unroll 3
    for (int j = 0; j < H; j++) sum = fmaf(s->wlin[j], s->hcat[103 + j][b], sum);
    return sum;
}

__global__ void __launch_bounds__(TPB, 1)
lstm_seq_kernel(const float *__restrict__ input,
                const float *__restrict__ W_ih1, const float *__restrict__ W_hh1,
                const float *__restrict__ b_ih1, const float *__restrict__ b_hh1,
                const float *__restrict__ W_ih2, const float *__restrict__ W_hh2,
                const float *__restrict__ b_ih2, const float *__restrict__ b_hh2,
                const float *__restrict__ W_ih3, const float *__restrict__ W_hh3,
                const float *__restrict__ b_ih3, const float *__restrict__ b_hh3,
                const float *__restrict__ W_lin, const float *__restrict__ b_lin,
                float *__restrict__ out) {
    extern __shared__ char raw[];
    Smem *s = (Smem *)raw;

    const int tid = threadIdx.x;
    const int b0  = blockIdx.x * BB;
    const int L   = tid >> 8;        // layer block of 256 lanes
    const int l   = tid & 255;
    const bool gate_lane = (l < 204);
    const int  p     = gate_lane ? (l >> 1) : 101;   // gate pair 0..101
    const int  khalf = l & 1;                        // k-half
    const int  j     = p >> 1;
    const int  sel   = p & 1;
    const int  q     = sel * 2 + khalf;              // batch slice (2 elems)
    const bool head_lane = (L == 0) && (l >= 204) && (l < 204 + BB);
    const bool xf_lane   = (L == 1) && (l >= 204) && (l < 204 + BB);

    // ---- one-time staging (pair (ga,gb) = (j+sel*51, j+sel*51+102)) ----
    for (int idx = tid; idx < (H + 1) * 102; idx += TPB) {
        int k = idx / 102, l2 = idx % 102;
        int ga = (l2 >> 1) + (l2 & 1) * 51, gb = ga + 102;
        float2 v;
        if (k == 0) v = make_float2(W_ih1[ga], W_ih1[gb]);
        else        v = make_float2(W_hh1[ga * H + k - 1], W_hh1[gb * H + k - 1]);
        s->W1[k][l2] = v;
    }
    for (int idx = tid; idx < 2 * H * 102; idx += TPB) {
        int k = idx / 102, l2 = idx % 102;
        int ga = (l2 >> 1) + (l2 & 1) * 51, gb = ga + 102;
        int kk = (k < H) ? k : k - H;
        const float *s2 = (k < H) ? W_ih2 : W_hh2;
        const float *s3 = (k < H) ? W_ih3 : W_hh3;
        s->W2[k][l2] = make_float2(s2[ga * H + kk], s2[gb * H + kk]);
        s->W3[k][l2] = make_float2(s3[ga * H + kk], s3[gb * H + kk]);
    }
    for (int idx = tid; idx < 3 * 102; idx += TPB) {
        int ly = idx / 102, l2 = idx % 102;
        int ga = (l2 >> 1) + (l2 & 1) * 51, gb = ga + 102;
        const float *bi = (ly == 0) ? b_ih1 : (ly == 1) ? b_ih2 : b_ih3;
        const float *bh = (ly == 0) ? b_hh1 : (ly == 1) ? b_hh2 : b_hh3;
        s->bp[ly][l2] = make_float2(bi[ga] + bh[ga], bi[gb] + bh[gb]);
    }
    if (tid < H) s->wlin[tid] = W_lin[tid];
    if (tid == 0) s->blin = b_lin[0];
    for (int idx = tid; idx < 153 * BB; idx += TPB) (&s->hcat[1][0])[idx] = 0.0f;
    if (tid < BB) s->hcat[0][tid] = input[(size_t)(b0 + tid) * T_IN];  // x(0)
    __syncthreads();

    float creg[2] = {0.f, 0.f};

    // ===== pipelined main loop: tick t -> L1@t, L2@t-1, L3@t-2 =====
    for (int t = 0; t < NTICK; t++) {
        ull   acc[8] = {};
        float xr = 0.0f;
        if (gate_lane) {
            if (khalf == 0) {
                float2 bv = s->bp[L][p];
                ull bx = pack2(bv.x), by = pack2(bv.y);
#pragma unroll
                for (int i = 0; i < 4; i++) { acc[i] = bx; acc[4 + i] = by; }
            }
            if (L == 0) {
                const int k0 = khalf * 26, k1 = k0 + 26;   // K=52 rows [x|h1]
#pragma unroll 2
                for (int k = k0; k < k1; k++) mac8(acc, s->W1[k][p], &s->hcat[k][0]);
            } else if (L == 1) {
                const int k0 = khalf * 51, k1 = k0 + 51;   // rows [h1|h2]
#pragma unroll 3
                for (int k = k0; k < k1; k++) mac8(acc, s->W2[k][p], &s->hcat[1 + k][0]);
            } else {
                const int k0 = khalf * 51, k1 = k0 + 51;   // rows [h2|h3]
#pragma unroll 3
                for (int k = k0; k < k1; k++) mac8(acc, s->W3[k][p], &s->hcat[52 + k][0]);
            }
        } else if (head_lane && t >= 3) {
            int b = l - 204;
            out[(size_t)(b0 + b) * T_TOT + (t - 3)] = head_dot(s, b);
        } else if (xf_lane && t + 1 < T_IN) {
            xr = input[(size_t)(b0 + l - 204) * T_IN + t + 1];
        }
        // combine k-halves, then exchange with gate-pair partner
        ull prt[8];
#pragma unroll
        for (int i = 0; i < 8; i++)
            acc[i] = add2(acc[i], __shfl_xor_sync(0xffffffffu, acc[i], 1));
#pragma unroll
        for (int i = 0; i < 8; i++)
            prt[i] = __shfl_xor_sync(0xffffffffu, acc[i], 2);

        const bool valid = gate_lane &&
            ((L == 0) ? (t <= T_IN - 1)
                      : (L == 1) ? (t >= 1 && t <= T_IN) : (t >= 2));
        float hn[2];
        if (valid) cell2(acc, prt, sel, khalf, creg, hn);
        __syncthreads();
        if (valid) *(float2 *)&s->hcat[1 + L * H + j][2 * q] = make_float2(hn[0], hn[1]);
        if (xf_lane && t + 1 < T_IN) s->hcat[0][l - 204] = xr;
        __syncthreads();
    }

    // ---- drain: park c-state, out(511), first autoregressive input ----
    if (gate_lane) *(float2 *)&s->c[L * H + j][2 * q] = make_float2(creg[0], creg[1]);
    if (tid < BB) {
        float v = head_dot(s, tid);
        out[(size_t)(b0 + tid) * T_TOT + (T_IN - 1)] = v;
        s->hcat[0][tid] = v;
    }
    __syncthreads();

    // ===== autoregressive future: wide lanes, k-thirds in adjacent lanes =====
    const int  m    = tid & 31, w5 = tid >> 5;
    const int  fpr  = w5 * 10 + m / 3;
    const int  fq   = m % 3;
    const bool fact = (tid < 384) && (m < 30) && (fpr < 102);
    const int  fp   = fact ? fpr : 101;
    const int  fj   = fp >> 1, fsel = fp & 1;
    const int  psrc = (3 * ((fp ^ 1) - w5 * 10)) & 31;

    for (int fs = 0; fs < T_FUT; fs++) {
#pragma unroll
        for (int lay = 0; lay < 3; lay++) {
            const float2(*W)[102];
            const float(*V)[BB];
            int k0, k1;
            if (lay == 0)      { W = s->W1; V = s->hcat;
                                 k0 = (fq == 0) ? 0 : (fq == 1) ? 18 : 35;
                                 k1 = (fq == 0) ? 18 : (fq == 1) ? 35 : 52; }
            else if (lay == 1) { W = s->W2; V = s->hcat + 1;  k0 = fq * 34; k1 = k0 + 34; }
            else               { W = s->W3; V = s->hcat + 52; k0 = fq * 34; k1 = k0 + 34; }
            ull acc[8] = {};
            if (fact) {
                if (fq == 0) {
                    float2 bv = s->bp[lay][fp];
                    ull bx = pack2(bv.x), by = pack2(bv.y);
#pragma unroll
                    for (int i = 0; i < 4; i++) { acc[i] = bx; acc[4 + i] = by; }
                }
#pragma unroll 2
                for (int k = k0; k < k1; k++) mac8(acc, W[k][fp], &V[k][0]);
            }
            ull prt[8];
#pragma unroll
            for (int i = 0; i < 8; i++) {
                ull t1 = __shfl_down_sync(0xffffffffu, acc[i], 1);
                ull t2 = __shfl_down_sync(0xffffffffu, acc[i], 2);
                acc[i] = add2(add2(acc[i], t1), t2);
            }
#pragma unroll
            for (int i = 0; i < 8; i++)
                prt[i] = __shfl_sync(0xffffffffu, acc[i], psrc);
            __syncthreads();
            if (fact && fq == 0) {
                float4 cv = *(float4 *)&s->c[lay * H + fj][fsel * 4];
                float cr[4] = {cv.x, cv.y, cv.z, cv.w};
                float hn[4];
                cell4(acc, prt, fsel, cr, hn);
                *(float4 *)&s->c[lay * H + fj][fsel * 4] =
                    make_float4(cr[0], cr[1], cr[2], cr[3]);
                *(float4 *)&s->hcat[1 + lay * H + fj][fsel * 4] =
                    make_float4(hn[0], hn[1], hn[2], hn[3]);
            }
            __syncthreads();
        }
        if (tid < BB) {
            float v = head_dot(s, tid);
            out[(size_t)(b0 + tid) * T_TOT + T_IN + fs] = v;
            s->hcat[0][tid] = v;
        }
        __syncthreads();
    }
}

extern "C" void kernel_launch(void *const *d_in, const int *in_sizes, int n_in,
                              void *d_out, int out_size) {
    (void)in_sizes; (void)n_in; (void)out_size;
    cudaFuncSetAttribute(lstm_seq_kernel,
                         cudaFuncAttributeMaxDynamicSharedMemorySize,
                         (int)sizeof(Smem));
    lstm_seq_kernel<<<NCTA, TPB, sizeof(Smem)>>>(
        (const float *)d_in[0],
        (const float *)d_in[1], (const float *)d_in[2],
        (const float *)d_in[3], (const float *)d_in[4],
        (const float *)d_in[5], (const float *)d_in[6],
        (const float *)d_in[7], (const float *)d_in[8],
        (const float *)d_in[9], (const float *)d_in[10],
        (const float *)d_in[11], (const float *)d_in[12],
        (const float *)d_in[13], (const float *)d_in[14],
        (float *)d_out);
}

// round 11
// speedup vs baseline: 1.3604x; 1.0827x over previous
#include <cuda_runtime.h>

#define H     51
#define G     204
#define BB    8
#define TPB   384
#define NCTA  128
#define T_IN  512
#define T_FUT 64
#define T_TOT 576
#define NTICK 514
#define K1P   56      // L1 K padded (52 real)
#define K2P   104     // L2/L3 K padded (102 real)

typedef unsigned long long ull;

struct __align__(16) Smem {
    float2 W1[K1P][102];   // k=0: W_ih1; k=1..51: W_hh1 col k-1; rows 52..55 zero
    float2 W2[K2P][102];   // 0..50 W_ih2, 51..101 W_hh2, 102..103 zero
    float2 W3[K2P][102];
    float2 bp[3][102];
    float  wlin[52];
    float  blin;
    float  padA[3];
    float  hcat[156][BB];  // 0=x; 1..51 h1; 52..102 h2; 103..153 h3; 154..155 zero
    float  c[3 * H][BB];   // c-state parking for the future phase
};

__device__ __forceinline__ ull pack2(float x) {
    ull r; asm("mov.b64 %0, {%1, %1};" : "=l"(r) : "f"(x)); return r;
}
__device__ __forceinline__ void unpack2(ull v, float &a, float &b) {
    asm("mov.b64 {%0, %1}, %2;" : "=f"(a), "=f"(b) : "l"(v));
}
__device__ __forceinline__ ull fma2(ull a, ull b, ull c) {
    ull d; asm("fma.rn.f32x2 %0, %1, %2, %3;" : "=l"(d) : "l"(a), "l"(b), "l"(c)); return d;
}
__device__ __forceinline__ ull add2(ull a, ull b) {
    ull d; asm("add.rn.f32x2 %0, %1, %2;" : "=l"(d) : "l"(a), "l"(b)); return d;
}
__device__ __forceinline__ float sigf(float x) {
    return __fdividef(1.0f, 1.0f + __expf(-x));
}
__device__ __forceinline__ float tanh_(float x) {
    return 1.0f - __fdividef(2.0f, __expf(2.0f * x) + 1.0f);
}

__device__ __forceinline__ void mac8(ull acc[8], float2 w, const float *row) {
    ulonglong2 va = *(const ulonglong2 *)row;
    ulonglong2 vb = *(const ulonglong2 *)(row + 4);
    ull wx = pack2(w.x), wy = pack2(w.y);
    acc[0] = fma2(wx, va.x, acc[0]); acc[1] = fma2(wx, va.y, acc[1]);
    acc[2] = fma2(wx, vb.x, acc[2]); acc[3] = fma2(wx, vb.y, acc[3]);
    acc[4] = fma2(wy, va.x, acc[4]); acc[5] = fma2(wy, va.y, acc[5]);
    acc[6] = fma2(wy, vb.x, acc[6]); acc[7] = fma2(wy, vb.y, acc[7]);
}

// ---- software-pipelined gate loop: 4-k chunks, double buffered ----
__device__ __forceinline__ void ldc(const float2 (*__restrict__ W)[102],
                                    const float (*__restrict__ V)[BB],
                                    int k, int p,
                                    float2 w[4], ulonglong2 va[4], ulonglong2 vb[4]) {
#pragma unroll
    for (int i = 0; i < 4; i++) {
        w[i]  = W[k + i][p];
        va[i] = *(const ulonglong2 *)&V[k + i][0];
        vb[i] = *(const ulonglong2 *)&V[k + i][4];
    }
}
__device__ __forceinline__ void fmc(ull acc[8], const float2 w[4],
                                    const ulonglong2 va[4], const ulonglong2 vb[4]) {
#pragma unroll
    for (int i = 0; i < 4; i++) {
        ull wx = pack2(w[i].x), wy = pack2(w[i].y);
        acc[0] = fma2(wx, va[i].x, acc[0]); acc[1] = fma2(wx, va[i].y, acc[1]);
        acc[2] = fma2(wx, vb[i].x, acc[2]); acc[3] = fma2(wx, vb[i].y, acc[3]);
        acc[4] = fma2(wy, va[i].x, acc[4]); acc[5] = fma2(wy, va[i].y, acc[5]);
        acc[6] = fma2(wy, vb[i].x, acc[6]); acc[7] = fma2(wy, vb[i].y, acc[7]);
    }
}

template <int NC2>   // number of 8-k double-chunks (K = 8*NC2)
__device__ __forceinline__ void gates_pipe(const float2 (*__restrict__ W)[102],
                                           const float (*__restrict__ V)[BB],
                                           int p, ull acc[8]) {
    float2     wA[4], wB[4];
    ulonglong2 vaA[4], vbA[4], vaB[4], vbB[4];
    ldc(W, V, 0, p, wA, vaA, vbA);
#pragma unroll 1
    for (int c = 0; c < NC2 - 1; c++) {
        ldc(W, V, 8 * c + 4, p, wB, vaB, vbB);
        fmc(acc, wA, vaA, vbA);
        ldc(W, V, 8 * c + 8, p, wA, vaA, vbA);
        fmc(acc, wB, vaB, vbB);
    }
    ldc(W, V, 8 * (NC2 - 1) + 4, p, wB, vaB, vbB);
    fmc(acc, wA, vaA, vbA);
    fmc(acc, wB, vaB, vbB);
}

// cell update for 4 batch elems; sel branch keeps register indices compile-time
__device__ __forceinline__ void cell4(const ull acc[8], const ull prt[8], int sel,
                                      float creg[4], float hn[4]) {
    ull iv0, iv1, gv0, gv1, fv0, fv1, ov0, ov1;
    if (sel == 0) {
        iv0 = acc[0]; iv1 = acc[1]; gv0 = acc[4]; gv1 = acc[5];
        fv0 = prt[0]; fv1 = prt[1]; ov0 = prt[4]; ov1 = prt[5];
    } else {
        iv0 = prt[2]; iv1 = prt[3]; gv0 = prt[6]; gv1 = prt[7];
        fv0 = acc[2]; fv1 = acc[3]; ov0 = acc[6]; ov1 = acc[7];
    }
    float ig[4], fg[4], gg[4], og[4];
    unpack2(iv0, ig[0], ig[1]); unpack2(iv1, ig[2], ig[3]);
    unpack2(fv0, fg[0], fg[1]); unpack2(fv1, fg[2], fg[3]);
    unpack2(gv0, gg[0], gg[1]); unpack2(gv1, gg[2], gg[3]);
    unpack2(ov0, og[0], og[1]); unpack2(ov1, og[2], og[3]);
#pragma unroll
    for (int u = 0; u < 4; u++) {
        float cn = sigf(fg[u]) * creg[u] + sigf(ig[u]) * tanh_(gg[u]);
        hn[u]    = sigf(og[u]) * tanh_(cn);
        creg[u]  = cn;
    }
}

__device__ __forceinline__ float head_dot(const Smem *s, int b) {
    float sum = s->blin;
#pragma unroll 3
    for (int j = 0; j < H; j++) sum = fmaf(s->wlin[j], s->hcat[103 + j][b], sum);
    return sum;
}

__global__ void __launch_bounds__(TPB, 1)
lstm_seq_kernel(const float *__restrict__ input,
                const float *__restrict__ W_ih1, const float *__restrict__ W_hh1,
                const float *__restrict__ b_ih1, const float *__restrict__ b_hh1,
                const float *__restrict__ W_ih2, const float *__restrict__ W_hh2,
                const float *__restrict__ b_ih2, const float *__restrict__ b_hh2,
                const float *__restrict__ W_ih3, const float *__restrict__ W_hh3,
                const float *__restrict__ b_ih3, const float *__restrict__ b_hh3,
                const float *__restrict__ W_lin, const float *__restrict__ b_lin,
                float *__restrict__ out) {
    extern __shared__ char raw[];
    Smem *s = (Smem *)raw;

    const int tid = threadIdx.x;
    const int b0  = blockIdx.x * BB;
    const int L   = tid >> 7;       // layer block: warps 0-3 / 4-7 / 8-11
    const int l   = tid & 127;
    const int lc  = (l < 102) ? l : 101;
    const int j   = lc >> 1;
    const int sel = lc & 1;
    const bool gate_lane = (l < 102);
    const bool head_lane = (L == 0) && (l >= 102) && (l < 102 + BB);
    const bool xf_lane   = (L == 1) && (l >= 102) && (l < 102 + BB);

    // ---- one-time staging (pair (ga,gb) = (j+sel*51, j+sel*51+102)) ----
    for (int idx = tid; idx < K1P * 102; idx += TPB) {
        int k = idx / 102, l2 = idx % 102;
        int ga = (l2 >> 1) + (l2 & 1) * 51, gb = ga + 102;
        float2 v = make_float2(0.f, 0.f);
        if (k == 0)      v = make_float2(W_ih1[ga], W_ih1[gb]);
        else if (k < 52) v = make_float2(W_hh1[ga * H + k - 1], W_hh1[gb * H + k - 1]);
        s->W1[k][l2] = v;
    }
    for (int idx = tid; idx < K2P * 102; idx += TPB) {
        int k = idx / 102, l2 = idx % 102;
        int ga = (l2 >> 1) + (l2 & 1) * 51, gb = ga + 102;
        float2 v2 = make_float2(0.f, 0.f), v3 = v2;
        if (k < 2 * H) {
            int kk = (k < H) ? k : k - H;
            const float *s2 = (k < H) ? W_ih2 : W_hh2;
            const float *s3 = (k < H) ? W_ih3 : W_hh3;
            v2 = make_float2(s2[ga * H + kk], s2[gb * H + kk]);
            v3 = make_float2(s3[ga * H + kk], s3[gb * H + kk]);
        }
        s->W2[k][l2] = v2;
        s->W3[k][l2] = v3;
    }
    for (int idx = tid; idx < 3 * 102; idx += TPB) {
        int ly = idx / 102, l2 = idx % 102;
        int ga = (l2 >> 1) + (l2 & 1) * 51, gb = ga + 102;
        const float *bi = (ly == 0) ? b_ih1 : (ly == 1) ? b_ih2 : b_ih3;
        const float *bh = (ly == 0) ? b_hh1 : (ly == 1) ? b_hh2 : b_hh3;
        s->bp[ly][l2] = make_float2(bi[ga] + bh[ga], bi[gb] + bh[gb]);
    }
    if (tid < H) s->wlin[tid] = W_lin[tid];
    if (tid == 0) s->blin = b_lin[0];
    for (int idx = tid; idx < 155 * BB; idx += TPB) (&s->hcat[1][0])[idx] = 0.0f;
    if (tid < BB) s->hcat[0][tid] = input[(size_t)(b0 + tid) * T_IN];  // x(0)
    __syncthreads();

    float creg[4] = {0.f, 0.f, 0.f, 0.f};

    // ===== pipelined main loop: tick t -> L1@t, L2@t-1, L3@t-2 =====
    for (int t = 0; t < NTICK; t++) {
        ull   acc[8];
        float xr = 0.0f;
        if (gate_lane) {
            float2 bv = s->bp[L][lc];
            ull bx = pack2(bv.x), by = pack2(bv.y);
#pragma unroll
            for (int i = 0; i < 4; i++) { acc[i] = bx; acc[4 + i] = by; }
            if (L == 0)      gates_pipe<7>(s->W1, s->hcat, lc, acc);       // [x|h1]
            else if (L == 1) gates_pipe<13>(s->W2, &s->hcat[1], lc, acc);  // [h1|h2]
            else             gates_pipe<13>(s->W3, &s->hcat[52], lc, acc); // [h2|h3]
        } else {
#pragma unroll
            for (int i = 0; i < 8; i++) acc[i] = 0ull;
            if (head_lane && t >= 3) {
                int b = l - 102;
                out[(size_t)(b0 + b) * T_TOT + (t - 3)] = head_dot(s, b);
            } else if (xf_lane && t + 1 < T_IN) {
                xr = input[(size_t)(b0 + l - 102) * T_IN + t + 1];
            }
        }
        ull prt[8];
#pragma unroll
        for (int i = 0; i < 8; i++) prt[i] = __shfl_xor_sync(0xffffffffu, acc[i], 1);

        const bool valid = gate_lane &&
            ((L == 0) ? (t <= T_IN - 1)
                      : (L == 1) ? (t >= 1 && t <= T_IN) : (t >= 2));
        float hn[4];
        if (valid) cell4(acc, prt, sel, creg, hn);
        __syncthreads();
        if (valid)
            *(float4 *)&s->hcat[1 + L * H + j][sel * 4] =
                make_float4(hn[0], hn[1], hn[2], hn[3]);
        if (xf_lane && t + 1 < T_IN) s->hcat[0][l - 102] = xr;
        __syncthreads();
    }

    // ---- drain: park c-state, out(511), first autoregressive input ----
    if (gate_lane)
        *(float4 *)&s->c[L * H + j][sel * 4] =
            make_float4(creg[0], creg[1], creg[2], creg[3]);
    if (tid < BB) {
        float v = head_dot(s, tid);
        out[(size_t)(b0 + tid) * T_TOT + (T_IN - 1)] = v;
        s->hcat[0][tid] = v;
    }
    __syncthreads();

    // ===== autoregressive future: wide lanes, k-thirds in adjacent lanes =====
    const int  m    = tid & 31, w5 = tid >> 5;
    const int  fpr  = w5 * 10 + m / 3;
    const int  fq   = m % 3;
    const bool fact = (m < 30) && (fpr < 102);
    const int  fp   = fact ? fpr : 101;
    const int  fj   = fp >> 1, fsel = fp & 1;
    const int  psrc = (3 * ((fp ^ 1) - w5 * 10)) & 31;

    for (int fs = 0; fs < T_FUT; fs++) {
#pragma unroll
        for (int lay = 0; lay < 3; lay++) {
            const float2(*W)[102];
            const float(*V)[BB];
            int k0, k1;
            if (lay == 0)      { W = s->W1; V = s->hcat;
                                 k0 = (fq == 0) ? 0 : (fq == 1) ? 18 : 35;
                                 k1 = (fq == 0) ? 18 : (fq == 1) ? 35 : 52; }
            else if (lay == 1) { W = s->W2; V = s->hcat + 1;  k0 = fq * 34; k1 = k0 + 34; }
            else               { W = s->W3; V = s->hcat + 52; k0 = fq * 34; k1 = k0 + 34; }
            ull acc[8] = {};
            if (fact) {
                if (fq == 0) {
                    float2 bv = s->bp[lay][fp];
                    ull bx = pack2(bv.x), by = pack2(bv.y);
#pragma unroll
                    for (int i = 0; i < 4; i++) { acc[i] = bx; acc[4 + i] = by; }
                }
#pragma unroll 2
                for (int k = k0; k < k1; k++) mac8(acc, W[k][fp], &V[k][0]);
            }
            ull prt[8];
#pragma unroll
            for (int i = 0; i < 8; i++) {
                ull t1 = __shfl_down_sync(0xffffffffu, acc[i], 1);
                ull t2 = __shfl_down_sync(0xffffffffu, acc[i], 2);
                acc[i] = add2(add2(acc[i], t1), t2);
            }
#pragma unroll
            for (int i = 0; i < 8; i++)
                prt[i] = __shfl_sync(0xffffffffu, acc[i], psrc);
            __syncthreads();
            if (fact && fq == 0) {
                float4 cv = *(float4 *)&s->c[lay * H + fj][fsel * 4];
                float cr[4] = {cv.x, cv.y, cv.z, cv.w};
                float hn[4];
                cell4(acc, prt, fsel, cr, hn);
                *(float4 *)&s->c[lay * H + fj][fsel * 4] =
                    make_float4(cr[0], cr[1], cr[2], cr[3]);
                *(float4 *)&s->hcat[1 + lay * H + fj][fsel * 4] =
                    make_float4(hn[0], hn[1], hn[2], hn[3]);
            }
            __syncthreads();
        }
        if (tid < BB) {
            float v = head_dot(s, tid);
            out[(size_t)(b0 + tid) * T_TOT + T_IN + fs] = v;
            s->hcat[0][tid] = v;
        }
        __syncthreads();
    }
}

extern "C" void kernel_launch(void *const *d_in, const int *in_sizes, int n_in,
                              void *d_out, int out_size) {
    (void)in_sizes; (void)n_in; (void)out_size;
    cudaFuncSetAttribute(lstm_seq_kernel,
                         cudaFuncAttributeMaxDynamicSharedMemorySize,
                         (int)sizeof(Smem));
    lstm_seq_kernel<<<NCTA, TPB, sizeof(Smem)>>>(
        (const float *)d_in[0],
        (const float *)d_in[1], (const float *)d_in[2],
        (const float *)d_in[3], (const float *)d_in[4],
        (const float *)d_in[5], (const float *)d_in[6],
        (const float *)d_in[7], (const float *)d_in[8],
        (const float *)d_in[9], (const float *)d_in[10],
        (const float *)d_in[11], (const float *)d_in[12],
        (const float *)d_in[13], (const float *)d_in[14],
        (float *)d_out);
}

// round 12
// speedup vs baseline: 1.4071x; 1.0343x over previous
#include <cuda_runtime.h>

#define H     51
#define G     204
#define BB    8
#define TPB   384
#define NCTA  128
#define T_IN  512
#define T_FUT 64
#define T_TOT 576
#define NTICK 514

typedef unsigned long long ull;

struct __align__(16) Smem {
    float2 W1[H + 1][102];   // k=0: W_ih1; k=1..51: W_hh1 col k-1; pair (ga,gb)
    float2 W2[2 * H][102];   // k=0..50: W_ih2 col k; 51..101: W_hh2 col k-51
    float2 W3[2 * H][102];
    float2 bp[3][102];       // bias pairs
    float  wlin[52];
    float  blin;
    float  padA[3];
    float  hcat[154][BB];    // row 0 = x; 1..51 h1; 52..102 h2; 103..153 h3
    float  c[3 * H][BB];     // c-state parking for the future phase
};

__device__ __forceinline__ ull pack2(float x) {
    ull r; asm("mov.b64 %0, {%1, %1};" : "=l"(r) : "f"(x)); return r;
}
__device__ __forceinline__ void unpack2(ull v, float &a, float &b) {
    asm("mov.b64 {%0, %1}, %2;" : "=f"(a), "=f"(b) : "l"(v));
}
__device__ __forceinline__ ull fma2(ull a, ull b, ull c) {
    ull d; asm("fma.rn.f32x2 %0, %1, %2, %3;" : "=l"(d) : "l"(a), "l"(b), "l"(c)); return d;
}
__device__ __forceinline__ ull add2(ull a, ull b) {
    ull d; asm("add.rn.f32x2 %0, %1, %2;" : "=l"(d) : "l"(a), "l"(b)); return d;
}
__device__ __forceinline__ float sigf(float x) {
    return __fdividef(1.0f, 1.0f + __expf(-x));
}
__device__ __forceinline__ float tanh_(float x) {
    return 1.0f - __fdividef(2.0f, __expf(2.0f * x) + 1.0f);
}

// gate_a x 8bb (acc[0..3]) and gate_b x 8bb (acc[4..7]) vs broadcast state row
__device__ __forceinline__ void mac8(ull acc[8], float2 w, const float *row) {
    ulonglong2 va = *(const ulonglong2 *)row;
    ulonglong2 vb = *(const ulonglong2 *)(row + 4);
    ull wx = pack2(w.x), wy = pack2(w.y);
    acc[0] = fma2(wx, va.x, acc[0]); acc[1] = fma2(wx, va.y, acc[1]);
    acc[2] = fma2(wx, vb.x, acc[2]); acc[3] = fma2(wx, vb.y, acc[3]);
    acc[4] = fma2(wy, va.x, acc[4]); acc[5] = fma2(wy, va.y, acc[5]);
    acc[6] = fma2(wy, vb.x, acc[6]); acc[7] = fma2(wy, vb.y, acc[7]);
}

// gates for layer `lay`, thread pair-slot lc
__device__ __forceinline__ void layer_gates(const Smem *s, int lay, int lc, ull acc[8]) {
    float2 bv = s->bp[lay][lc];
    ull bx = pack2(bv.x), by = pack2(bv.y);
#pragma unroll
    for (int i = 0; i < 4; i++) { acc[i] = bx; acc[4 + i] = by; }
    if (lay == 0) {
#pragma unroll 4
        for (int k = 0; k < H + 1; k++) mac8(acc, s->W1[k][lc], &s->hcat[k][0]);
    } else if (lay == 1) {
#pragma unroll 3
        for (int k = 0; k < 2 * H; k++) mac8(acc, s->W2[k][lc], &s->hcat[1 + k][0]);
    } else {
#pragma unroll 3
        for (int k = 0; k < 2 * H; k++) mac8(acc, s->W3[k][lc], &s->hcat[52 + k][0]);
    }
}

// cell update for 4 batch elems; sel branch keeps register indices compile-time
__device__ __forceinline__ void cell4(const ull acc[8], const ull prt[8], int sel,
                                      float creg[4], float hn[4]) {
    ull iv0, iv1, gv0, gv1, fv0, fv1, ov0, ov1;
    if (sel == 0) {
        iv0 = acc[0]; iv1 = acc[1]; gv0 = acc[4]; gv1 = acc[5];
        fv0 = prt[0]; fv1 = prt[1]; ov0 = prt[4]; ov1 = prt[5];
    } else {
        iv0 = prt[2]; iv1 = prt[3]; gv0 = prt[6]; gv1 = prt[7];
        fv0 = acc[2]; fv1 = acc[3]; ov0 = acc[6]; ov1 = acc[7];
    }
    float ig[4], fg[4], gg[4], og[4];
    unpack2(iv0, ig[0], ig[1]); unpack2(iv1, ig[2], ig[3]);
    unpack2(fv0, fg[0], fg[1]); unpack2(fv1, fg[2], fg[3]);
    unpack2(gv0, gg[0], gg[1]); unpack2(gv1, gg[2], gg[3]);
    unpack2(ov0, og[0], og[1]); unpack2(ov1, og[2], og[3]);
#pragma unroll
    for (int u = 0; u < 4; u++) {
        float cn = sigf(fg[u]) * creg[u] + sigf(ig[u]) * tanh_(gg[u]);
        hn[u]    = sigf(og[u]) * tanh_(cn);
        creg[u]  = cn;
    }
}

__device__ __forceinline__ float head_dot(const Smem *s, int b) {
    float sum = s->blin;
#pragma unroll 3
    for (int j = 0; j < H; j++) sum = fmaf(s->wlin[j], s->hcat[103 + j][b], sum);
    return sum;
}

__global__ void __launch_bounds__(TPB, 1)
lstm_seq_kernel(const float *__restrict__ input,
                const float *__restrict__ W_ih1, const float *__restrict__ W_hh1,
                const float *__restrict__ b_ih1, const float *__restrict__ b_hh1,
                const float *__restrict__ W_ih2, const float *__restrict__ W_hh2,
                const float *__restrict__ b_ih2, const float *__restrict__ b_hh2,
                const float *__restrict__ W_ih3, const float *__restrict__ W_hh3,
                const float *__restrict__ b_ih3, const float *__restrict__ b_hh3,
                const float *__restrict__ W_lin, const float *__restrict__ b_lin,
                float *__restrict__ out) {
    extern __shared__ char raw[];
    Smem *s = (Smem *)raw;

    const int tid = threadIdx.x;
    const int b0  = blockIdx.x * BB;
    const int L   = tid >> 7;       // layer block: warps 0-3 / 4-7 / 8-11
    const int l   = tid & 127;      // pair slot if < 102
    const int lc  = (l < 102) ? l : 101;
    const int j   = lc >> 1;
    const int sel = lc & 1;
    const bool gate_lane = (l < 102);
    const bool head_lane = (L == 0) && (l >= 102) && (l < 102 + BB);
    const bool xf_lane   = (L == 1) && (l >= 102) && (l < 102 + BB);

    // ---- one-time staging (pair (ga,gb) = (j+sel*51, j+sel*51+102)) ----
    for (int idx = tid; idx < (H + 1) * 102; idx += TPB) {
        int k = idx / 102, l2 = idx % 102;
        int ga = (l2 >> 1) + (l2 & 1) * 51, gb = ga + 102;
        float2 v;
        if (k == 0) v = make_float2(W_ih1[ga], W_ih1[gb]);
        else        v = make_float2(W_hh1[ga * H + k - 1], W_hh1[gb * H + k - 1]);
        s->W1[k][l2] = v;
    }
    for (int idx = tid; idx < 2 * H * 102; idx += TPB) {
        int k = idx / 102, l2 = idx % 102;
        int ga = (l2 >> 1) + (l2 & 1) * 51, gb = ga + 102;
        int kk = (k < H) ? k : k - H;
        const float *s2 = (k < H) ? W_ih2 : W_hh2;
        const float *s3 = (k < H) ? W_ih3 : W_hh3;
        s->W2[k][l2] = make_float2(s2[ga * H + kk], s2[gb * H + kk]);
        s->W3[k][l2] = make_float2(s3[ga * H + kk], s3[gb * H + kk]);
    }
    for (int idx = tid; idx < 3 * 102; idx += TPB) {
        int ly = idx / 102, l2 = idx % 102;
        int ga = (l2 >> 1) + (l2 & 1) * 51, gb = ga + 102;
        const float *bi = (ly == 0) ? b_ih1 : (ly == 1) ? b_ih2 : b_ih3;
        const float *bh = (ly == 0) ? b_hh1 : (ly == 1) ? b_hh2 : b_hh3;
        s->bp[ly][l2] = make_float2(bi[ga] + bh[ga], bi[gb] + bh[gb]);
    }
    if (tid < H) s->wlin[tid] = W_lin[tid];
    if (tid == 0) s->blin = b_lin[0];
    for (int idx = tid; idx < 153 * BB; idx += TPB) (&s->hcat[1][0])[idx] = 0.0f;
    if (tid < BB) s->hcat[0][tid] = input[(size_t)(b0 + tid) * T_IN];  // x(0)
    __syncthreads();

    float creg[4] = {0.f, 0.f, 0.f, 0.f};

    // ===== pipelined main loop: tick t -> L1@t, L2@t-1, L3@t-2 =====
    for (int t = 0; t < NTICK; t++) {
        ull   acc[8] = {};
        float xr = 0.0f;
        if (gate_lane) {
            if (L == 0)      layer_gates(s, 0, lc, acc);
            else if (L == 1) layer_gates(s, 1, lc, acc);
            else             layer_gates(s, 2, lc, acc);
        } else if (head_lane && t >= 3) {
            int b = l - 102;
            out[(size_t)(b0 + b) * T_TOT + (t - 3)] = head_dot(s, b);
        } else if (xf_lane && t + 1 < T_IN) {
            xr = input[(size_t)(b0 + l - 102) * T_IN + t + 1];
        }
        ull prt[8];
#pragma unroll
        for (int i = 0; i < 8; i++) prt[i] = __shfl_xor_sync(0xffffffffu, acc[i], 1);

        const bool valid = gate_lane &&
            ((L == 0) ? (t <= T_IN - 1)
                      : (L == 1) ? (t >= 1 && t <= T_IN) : (t >= 2));
        float hn[4];
        if (valid) cell4(acc, prt, sel, creg, hn);
        __syncthreads();
        if (valid)
            *(float4 *)&s->hcat[1 + L * H + j][sel * 4] =
                make_float4(hn[0], hn[1], hn[2], hn[3]);
        if (xf_lane && t + 1 < T_IN) s->hcat[0][l - 102] = xr;
        __syncthreads();
    }

    // ---- drain: park c-state, out(511), first autoregressive input ----
    if (gate_lane)
        *(float4 *)&s->c[L * H + j][sel * 4] =
            make_float4(creg[0], creg[1], creg[2], creg[3]);
    if (tid < BB) {
        float v = head_dot(s, tid);
        out[(size_t)(b0 + tid) * T_TOT + (T_IN - 1)] = v;
        s->hcat[0][tid] = v;
    }
    __syncthreads();

    // ===== autoregressive future: wide lanes, k-thirds in adjacent lanes =====
    const int  m    = tid & 31, w5 = tid >> 5;
    const int  fpr  = w5 * 10 + m / 3;
    const int  fq   = m % 3;
    const bool fact = (m < 30) && (fpr < 102);
    const int  fp   = fact ? fpr : 101;
    const int  fj   = fp >> 1, fsel = fp & 1;
    const int  psrc = (3 * ((fp ^ 1) - w5 * 10)) & 31;

    for (int fs = 0; fs < T_FUT; fs++) {
#pragma unroll
        for (int lay = 0; lay < 3; lay++) {
            const float2(*W)[102];
            const float(*V)[BB];
            int k0, k1;
            if (lay == 0)      { W = s->W1; V = s->hcat;
                                 k0 = (fq == 0) ? 0 : (fq == 1) ? 18 : 35;
                                 k1 = (fq == 0) ? 18 : (fq == 1) ? 35 : 52; }
            else if (lay == 1) { W = s->W2; V = s->hcat + 1;  k0 = fq * 34; k1 = k0 + 34; }
            else               { W = s->W3; V = s->hcat + 52; k0 = fq * 34; k1 = k0 + 34; }
            ull acc[8] = {};
            if (fact) {
                if (fq == 0) {
                    float2 bv = s->bp[lay][fp];
                    ull bx = pack2(bv.x), by = pack2(bv.y);
#pragma unroll
                    for (int i = 0; i < 4; i++) { acc[i] = bx; acc[4 + i] = by; }
                }
#pragma unroll 2
                for (int k = k0; k < k1; k++) mac8(acc, W[k][fp], &V[k][0]);
            }
            ull prt[8];
#pragma unroll
            for (int i = 0; i < 8; i++) {
                ull t1 = __shfl_down_sync(0xffffffffu, acc[i], 1);
                ull t2 = __shfl_down_sync(0xffffffffu, acc[i], 2);
                acc[i] = add2(add2(acc[i], t1), t2);
            }
#pragma unroll
            for (int i = 0; i < 8; i++)
                prt[i] = __shfl_sync(0xffffffffu, acc[i], psrc);
            __syncthreads();
            if (fact && fq == 0) {
                float4 cv = *(float4 *)&s->c[lay * H + fj][fsel * 4];
                float cr[4] = {cv.x, cv.y, cv.z, cv.w};
                float hn[4];
                cell4(acc, prt, fsel, cr, hn);
                *(float4 *)&s->c[lay * H + fj][fsel * 4] =
                    make_float4(cr[0], cr[1], cr[2], cr[3]);
                *(float4 *)&s->hcat[1 + lay * H + fj][fsel * 4] =
                    make_float4(hn[0], hn[1], hn[2], hn[3]);
            }
            __syncthreads();
        }
        if (tid < BB) {
            float v = head_dot(s, tid);
            out[(size_t)(b0 + tid) * T_TOT + T_IN + fs] = v;
            s->hcat[0][tid] = v;
        }
        __syncthreads();
    }
}

extern "C" void kernel_launch(void *const *d_in, const int *in_sizes, int n_in,
                              void *d_out, int out_size) {
    (void)in_sizes; (void)n_in; (void)out_size;
    cudaFuncSetAttribute(lstm_seq_kernel,
                         cudaFuncAttributeMaxDynamicSharedMemorySize,
                         (int)sizeof(Smem));
    lstm_seq_kernel<<<NCTA, TPB, sizeof(Smem)>>>(
        (const float *)d_in[0],
        (const float *)d_in[1], (const float *)d_in[2],
        (const float *)d_in[3], (const float *)d_in[4],
        (const float *)d_in[5], (const float *)d_in[6],
        (const float *)d_in[7], (const float *)d_in[8],
        (const float *)d_in[9], (const float *)d_in[10],
        (const float *)d_in[11], (const float *)d_in[12],
        (const float *)d_in[13], (const float *)d_in[14],
        (float *)d_out);
}

// round 13
// speedup vs baseline: 1.5434x; 1.0968x over previous
#include <cuda_runtime.h>

#define H     51
#define BB    8
#define TPB   384
#define NCTA  128
#define T_IN  512
#define T_FUT 64
#define T_TOT 576
#define NTICK 514

typedef unsigned long long ull;

struct __align__(16) Smem {
    float4     W1q[52][H];    // k=0: W_ih1; k=1..51: W_hh1 col k-1; (i,f,g,o) of unit j
    float4     W2q[102][H];   // k=0..50: W_ih2; 51..101: W_hh2
    float4     W3q[102][H];
    ulonglong2 bq[3][H];      // bias pairs {bi,bf},{bg,bo}
    ull        hdup[154][BB]; // {h,h} pairs; row0=x, 1..51=h1, 52..102=h2, 103..153=h3
    float      wlin[52];
    float      blin;
};

__device__ __forceinline__ ull pack2(float x) {
    ull r; asm("mov.b64 %0, {%1, %1};" : "=l"(r) : "f"(x)); return r;
}
__device__ __forceinline__ ull packf2(float a, float b) {
    ull r; asm("mov.b64 %0, {%1, %2};" : "=l"(r) : "f"(a), "f"(b)); return r;
}
__device__ __forceinline__ void unpack2(ull v, float &a, float &b) {
    asm("mov.b64 {%0, %1}, %2;" : "=f"(a), "=f"(b) : "l"(v));
}
__device__ __forceinline__ ull fma2(ull a, ull b, ull c) {
    ull d; asm("fma.rn.f32x2 %0, %1, %2, %3;" : "=l"(d) : "l"(a), "l"(b), "l"(c)); return d;
}
__device__ __forceinline__ float sigf(float x) {
    return __fdividef(1.0f, 1.0f + __expf(-x));
}
__device__ __forceinline__ float tanh_(float x) {
    return 1.0f - __fdividef(2.0f, __expf(2.0f * x) + 1.0f);
}

// per k: 1 LDS.128 weight quad (pre-paired) + 2 LDS.128 dup-state + 8 fma2
template <int K>
__device__ __forceinline__ void gloop(const float4 (*__restrict__ W)[H],
                                      const ull (*__restrict__ Vd)[BB],
                                      int j, int bh4, ull acc[8]) {
#pragma unroll 3
    for (int k = 0; k < K; k++) {
        ulonglong2 wv = *(const ulonglong2 *)&W[k][j];       // {wi,wf},{wg,wo}
        ulonglong2 h0 = *(const ulonglong2 *)&Vd[k][bh4];    // {h_b0,h_b0},{h_b1,h_b1}
        ulonglong2 h1 = *(const ulonglong2 *)&Vd[k][bh4 + 2];
        acc[0] = fma2(wv.x, h0.x, acc[0]); acc[1] = fma2(wv.x, h0.y, acc[1]);
        acc[2] = fma2(wv.x, h1.x, acc[2]); acc[3] = fma2(wv.x, h1.y, acc[3]);
        acc[4] = fma2(wv.y, h0.x, acc[4]); acc[5] = fma2(wv.y, h0.y, acc[5]);
        acc[6] = fma2(wv.y, h1.x, acc[6]); acc[7] = fma2(wv.y, h1.y, acc[7]);
    }
}

// thread-local cell: acc[b]={i_b,f_b}, acc[4+b]={g_b,o_b}; outputs duplicated h
__device__ __forceinline__ void cell_local(const ull acc[8], float creg[4], ull hnew[4]) {
#pragma unroll
    for (int b = 0; b < 4; b++) {
        float iv, fv, gv, ov;
        unpack2(acc[b],     iv, fv);
        unpack2(acc[4 + b], gv, ov);
        float cn = sigf(fv) * creg[b] + sigf(iv) * tanh_(gv);
        float hn = sigf(ov) * tanh_(cn);
        creg[b]  = cn;
        hnew[b]  = pack2(hn);
    }
}

__device__ __forceinline__ void hwrite(ull *dst, const ull hnew[4]) {
    ulonglong2 v0, v1;
    v0.x = hnew[0]; v0.y = hnew[1];
    v1.x = hnew[2]; v1.y = hnew[3];
    *(ulonglong2 *)dst       = v0;
    *(ulonglong2 *)(dst + 2) = v1;
}

__device__ __forceinline__ float head_dot(const Smem *s, int b) {
    float sum = s->blin;
#pragma unroll 3
    for (int jj = 0; jj < H; jj++)
        sum = fmaf(s->wlin[jj], ((const float *)&s->hdup[103 + jj][b])[0], sum);
    return sum;
}

__global__ void __launch_bounds__(TPB, 1)
lstm_seq_kernel(const float *__restrict__ input,
                const float *__restrict__ W_ih1, const float *__restrict__ W_hh1,
                const float *__restrict__ b_ih1, const float *__restrict__ b_hh1,
                const float *__restrict__ W_ih2, const float *__restrict__ W_hh2,
                const float *__restrict__ b_ih2, const float *__restrict__ b_hh2,
                const float *__restrict__ W_ih3, const float *__restrict__ W_hh3,
                const float *__restrict__ b_ih3, const float *__restrict__ b_hh3,
                const float *__restrict__ W_lin, const float *__restrict__ b_lin,
                float *__restrict__ out) {
    extern __shared__ char raw[];
    Smem *s = (Smem *)raw;

    const int tid = threadIdx.x;
    const int b0  = blockIdx.x * BB;
    const int L   = tid >> 7;       // layer block: warps 0-3 / 4-7 / 8-11
    const int l   = tid & 127;
    const bool gate_lane = (l < 102);
    const int  j   = gate_lane ? (l >> 1) : (H - 1);  // hidden unit
    const int  bh4 = (l & 1) * 4;                     // batch-half offset
    const bool head_lane = (L == 0) && (l >= 102) && (l < 102 + BB);
    const bool xf_lane   = (L == 1) && (l >= 102) && (l < 102 + BB);

    // ---- one-time staging: weight quads (i,f,g,o) per unit j ----
    for (int idx = tid; idx < 52 * H; idx += TPB) {
        int k = idx / H, jj = idx % H;
        float4 v;
        if (k == 0)
            v = make_float4(W_ih1[jj], W_ih1[jj + 51], W_ih1[jj + 102], W_ih1[jj + 153]);
        else
            v = make_float4(W_hh1[jj * H + k - 1],         W_hh1[(jj + 51) * H + k - 1],
                            W_hh1[(jj + 102) * H + k - 1], W_hh1[(jj + 153) * H + k - 1]);
        s->W1q[k][jj] = v;
    }
    for (int idx = tid; idx < 102 * H; idx += TPB) {
        int k = idx / H, jj = idx % H;
        int kk = (k < H) ? k : k - H;
        const float *s2 = (k < H) ? W_ih2 : W_hh2;
        const float *s3 = (k < H) ? W_ih3 : W_hh3;
        s->W2q[k][jj] = make_float4(s2[jj * H + kk],         s2[(jj + 51) * H + kk],
                                    s2[(jj + 102) * H + kk], s2[(jj + 153) * H + kk]);
        s->W3q[k][jj] = make_float4(s3[jj * H + kk],         s3[(jj + 51) * H + kk],
                                    s3[(jj + 102) * H + kk], s3[(jj + 153) * H + kk]);
    }
    for (int idx = tid; idx < 3 * H; idx += TPB) {
        int ly = idx / H, jj = idx % H;
        const float *bi = (ly == 0) ? b_ih1 : (ly == 1) ? b_ih2 : b_ih3;
        const float *bh = (ly == 0) ? b_hh1 : (ly == 1) ? b_hh2 : b_hh3;
        ulonglong2 bv;
        bv.x = packf2(bi[jj] + bh[jj],             bi[jj + 51] + bh[jj + 51]);
        bv.y = packf2(bi[jj + 102] + bh[jj + 102], bi[jj + 153] + bh[jj + 153]);
        s->bq[ly][jj] = bv;
    }
    if (tid < H) s->wlin[tid] = W_lin[tid];
    if (tid == 0) s->blin = b_lin[0];
    for (int idx = tid; idx < 153 * BB; idx += TPB) (&s->hdup[1][0])[idx] = 0ull;
    if (tid < BB) s->hdup[0][tid] = pack2(input[(size_t)(b0 + tid) * T_IN]);  // x(0)
    __syncthreads();

    float creg[4] = {0.f, 0.f, 0.f, 0.f};

    // ===== pipelined main loop: tick t -> L1@t, L2@t-1, L3@t-2 =====
    for (int t = 0; t < NTICK; t++) {
        ull   acc[8], hnew[4];
        float xr = 0.0f;
        const bool valid = gate_lane &&
            ((L == 0) ? (t <= T_IN - 1)
                      : (L == 1) ? (t >= 1 && t <= T_IN) : (t >= 2));
        if (gate_lane) {
            ulonglong2 bv = s->bq[L][j];
#pragma unroll
            for (int i = 0; i < 4; i++) { acc[i] = bv.x; acc[4 + i] = bv.y; }
            if (L == 0)      gloop<52>(s->W1q,  s->hdup,      j, bh4, acc);  // [x|h1]
            else if (L == 1) gloop<102>(s->W2q, s->hdup + 1,  j, bh4, acc);  // [h1|h2]
            else             gloop<102>(s->W3q, s->hdup + 52, j, bh4, acc);  // [h2|h3]
        } else if (head_lane && t >= 3) {
            int b = l - 102;
            out[(size_t)(b0 + b) * T_TOT + (t - 3)] = head_dot(s, b);
        } else if (xf_lane && t + 1 < T_IN) {
            xr = input[(size_t)(b0 + l - 102) * T_IN + t + 1];
        }
        if (valid) cell_local(acc, creg, hnew);
        __syncthreads();
        if (valid) hwrite(&s->hdup[1 + L * H + j][bh4], hnew);
        if (xf_lane && t + 1 < T_IN) s->hdup[0][l - 102] = pack2(xr);
        __syncthreads();
    }

    // ---- drain: out(511) + first autoregressive input ----
    if (tid < BB) {
        float v = head_dot(s, tid);
        out[(size_t)(b0 + tid) * T_TOT + (T_IN - 1)] = v;
        s->hdup[0][tid] = pack2(v);
    }
    __syncthreads();

    // ===== autoregressive future: layer-serial, thread-local cell =====
    for (int fs = 0; fs < T_FUT; fs++) {
#pragma unroll
        for (int lay = 0; lay < 3; lay++) {
            ull acc[8], hnew[4];
            const bool w = (L == lay) && gate_lane;
            if (w) {
                ulonglong2 bv = s->bq[lay][j];
#pragma unroll
                for (int i = 0; i < 4; i++) { acc[i] = bv.x; acc[4 + i] = bv.y; }
                if (lay == 0)      gloop<52>(s->W1q,  s->hdup,      j, bh4, acc);
                else if (lay == 1) gloop<102>(s->W2q, s->hdup + 1,  j, bh4, acc);
                else               gloop<102>(s->W3q, s->hdup + 52, j, bh4, acc);
                cell_local(acc, creg, hnew);
            }
            __syncthreads();
            if (w) hwrite(&s->hdup[1 + lay * H + j][bh4], hnew);
            __syncthreads();
        }
        if (tid < BB) {
            float v = head_dot(s, tid);
            out[(size_t)(b0 + tid) * T_TOT + T_IN + fs] = v;
            s->hdup[0][tid] = pack2(v);
        }
        __syncthreads();
    }
}

extern "C" void kernel_launch(void *const *d_in, const int *in_sizes, int n_in,
                              void *d_out, int out_size) {
    (void)in_sizes; (void)n_in; (void)out_size;
    cudaFuncSetAttribute(lstm_seq_kernel,
                         cudaFuncAttributeMaxDynamicSharedMemorySize,
                         (int)sizeof(Smem));
    lstm_seq_kernel<<<NCTA, TPB, sizeof(Smem)>>>(
        (const float *)d_in[0],
        (const float *)d_in[1], (const float *)d_in[2],
        (const float *)d_in[3], (const float *)d_in[4],
        (const float *)d_in[5], (const float *)d_in[6],
        (const float *)d_in[7], (const float *)d_in[8],
        (const float *)d_in[9], (const float *)d_in[10],
        (const float *)d_in[11], (const float *)d_in[12],
        (const float *)d_in[13], (const float *)d_in[14],
        (float *)d_out);
}

// round 14
// speedup vs baseline: 1.6177x; 1.0481x over previous
#include <cuda_runtime.h>

#define H     51
#define BB    8
#define TPB   384
#define NCTA  128
#define T_IN  512
#define T_FUT 64
#define T_TOT 576
#define NTICK 514

typedef unsigned long long ull;

struct __align__(16) Smem {
    float4     W1q[52][H];    // k=0: W_ih1; k=1..51: W_hh1 col k-1; (i,f,g,o) of unit j
    float4     W2q[102][H];   // k=0..50: W_ih2; 51..101: W_hh2
    float4     W3q[102][H];
    ulonglong2 bq[3][H];      // bias pairs {bi,bf},{bg,bo}
    ull        hdup[154][BB]; // {h,h} pairs; row0=x, 1..51=h1, 52..102=h2, 103..153=h3
    float      wlin[52];
    float      blin;
};

__device__ __forceinline__ ull pack2(float x) {
    ull r; asm("mov.b64 %0, {%1, %1};" : "=l"(r) : "f"(x)); return r;
}
__device__ __forceinline__ ull packf2(float a, float b) {
    ull r; asm("mov.b64 %0, {%1, %2};" : "=l"(r) : "f"(a), "f"(b)); return r;
}
__device__ __forceinline__ void unpack2(ull v, float &a, float &b) {
    asm("mov.b64 {%0, %1}, %2;" : "=f"(a), "=f"(b) : "l"(v));
}
__device__ __forceinline__ ull fma2(ull a, ull b, ull c) {
    ull d; asm("fma.rn.f32x2 %0, %1, %2, %3;" : "=l"(d) : "l"(a), "l"(b), "l"(c)); return d;
}
// hardware tanh (sm_75+): 1 MUFU op, rel err ~2^-11
__device__ __forceinline__ float tanh_(float x) {
    float y; asm("tanh.approx.f32 %0, %1;" : "=f"(y) : "f"(x)); return y;
}
__device__ __forceinline__ float sigf(float x) {
    return fmaf(tanh_(0.5f * x), 0.5f, 0.5f);
}

// per k: 1 LDS.128 weight quad (pre-paired) + 2 LDS.128 dup-state + 8 fma2
template <int K>
__device__ __forceinline__ void gloop(const float4 (*__restrict__ W)[H],
                                      const ull (*__restrict__ Vd)[BB],
                                      int j, int bh4, ull acc[8]) {
#pragma unroll 3
    for (int k = 0; k < K; k++) {
        ulonglong2 wv = *(const ulonglong2 *)&W[k][j];       // {wi,wf},{wg,wo}
        ulonglong2 h0 = *(const ulonglong2 *)&Vd[k][bh4];    // {h_b0,h_b0},{h_b1,h_b1}
        ulonglong2 h1 = *(const ulonglong2 *)&Vd[k][bh4 + 2];
        acc[0] = fma2(wv.x, h0.x, acc[0]); acc[1] = fma2(wv.x, h0.y, acc[1]);
        acc[2] = fma2(wv.x, h1.x, acc[2]); acc[3] = fma2(wv.x, h1.y, acc[3]);
        acc[4] = fma2(wv.y, h0.x, acc[4]); acc[5] = fma2(wv.y, h0.y, acc[5]);
        acc[6] = fma2(wv.y, h1.x, acc[6]); acc[7] = fma2(wv.y, h1.y, acc[7]);
    }
}

// thread-local cell: acc[b]={i_b,f_b}, acc[4+b]={g_b,o_b}; outputs duplicated h
__device__ __forceinline__ void cell_local(const ull acc[8], float creg[4], ull hnew[4]) {
#pragma unroll
    for (int b = 0; b < 4; b++) {
        float iv, fv, gv, ov;
        unpack2(acc[b],     iv, fv);
        unpack2(acc[4 + b], gv, ov);
        float cn = sigf(fv) * creg[b] + sigf(iv) * tanh_(gv);
        float hn = sigf(ov) * tanh_(cn);
        creg[b]  = cn;
        hnew[b]  = pack2(hn);
    }
}

__device__ __forceinline__ void hwrite(ull *dst, const ull hnew[4]) {
    ulonglong2 v0, v1;
    v0.x = hnew[0]; v0.y = hnew[1];
    v1.x = hnew[2]; v1.y = hnew[3];
    *(ulonglong2 *)dst       = v0;
    *(ulonglong2 *)(dst + 2) = v1;
}

__device__ __forceinline__ float head_dot(const Smem *s, int b) {
    float sum = s->blin;
#pragma unroll 3
    for (int jj = 0; jj < H; jj++)
        sum = fmaf(s->wlin[jj], ((const float *)&s->hdup[103 + jj][b])[0], sum);
    return sum;
}

__global__ void __launch_bounds__(TPB, 1)
lstm_seq_kernel(const float *__restrict__ input,
                const float *__restrict__ W_ih1, const float *__restrict__ W_hh1,
                const float *__restrict__ b_ih1, const float *__restrict__ b_hh1,
                const float *__restrict__ W_ih2, const float *__restrict__ W_hh2,
                const float *__restrict__ b_ih2, const float *__restrict__ b_hh2,
                const float *__restrict__ W_ih3, const float *__restrict__ W_hh3,
                const float *__restrict__ b_ih3, const float *__restrict__ b_hh3,
                const float *__restrict__ W_lin, const float *__restrict__ b_lin,
                float *__restrict__ out) {
    extern __shared__ char raw[];
    Smem *s = (Smem *)raw;

    const int tid = threadIdx.x;
    const int b0  = blockIdx.x * BB;
    const int L   = tid >> 7;       // layer block: warps 0-3 / 4-7 / 8-11
    const int l   = tid & 127;
    const bool gate_lane = (l < 102);
    const int  j   = gate_lane ? (l >> 1) : (H - 1);  // hidden unit
    const int  bh4 = (l & 1) * 4;                     // batch-half offset
    const bool head_lane = (L == 0) && (l >= 102) && (l < 102 + BB);
    const bool xf_lane   = (L == 1) && (l >= 102) && (l < 102 + BB);

    // ---- one-time staging: weight quads (i,f,g,o) per unit j ----
    for (int idx = tid; idx < 52 * H; idx += TPB) {
        int k = idx / H, jj = idx % H;
        float4 v;
        if (k == 0)
            v = make_float4(W_ih1[jj], W_ih1[jj + 51], W_ih1[jj + 102], W_ih1[jj + 153]);
        else
            v = make_float4(W_hh1[jj * H + k - 1],         W_hh1[(jj + 51) * H + k - 1],
                            W_hh1[(jj + 102) * H + k - 1], W_hh1[(jj + 153) * H + k - 1]);
        s->W1q[k][jj] = v;
    }
    for (int idx = tid; idx < 102 * H; idx += TPB) {
        int k = idx / H, jj = idx % H;
        int kk = (k < H) ? k : k - H;
        const float *s2 = (k < H) ? W_ih2 : W_hh2;
        const float *s3 = (k < H) ? W_ih3 : W_hh3;
        s->W2q[k][jj] = make_float4(s2[jj * H + kk],         s2[(jj + 51) * H + kk],
                                    s2[(jj + 102) * H + kk], s2[(jj + 153) * H + kk]);
        s->W3q[k][jj] = make_float4(s3[jj * H + kk],         s3[(jj + 51) * H + kk],
                                    s3[(jj + 102) * H + kk], s3[(jj + 153) * H + kk]);
    }
    for (int idx = tid; idx < 3 * H; idx += TPB) {
        int ly = idx / H, jj = idx % H;
        const float *bi = (ly == 0) ? b_ih1 : (ly == 1) ? b_ih2 : b_ih3;
        const float *bh = (ly == 0) ? b_hh1 : (ly == 1) ? b_hh2 : b_hh3;
        ulonglong2 bv;
        bv.x = packf2(bi[jj] + bh[jj],             bi[jj + 51] + bh[jj + 51]);
        bv.y = packf2(bi[jj + 102] + bh[jj + 102], bi[jj + 153] + bh[jj + 153]);
        s->bq[ly][jj] = bv;
    }
    if (tid < H) s->wlin[tid] = W_lin[tid];
    if (tid == 0) s->blin = b_lin[0];
    for (int idx = tid; idx < 153 * BB; idx += TPB) (&s->hdup[1][0])[idx] = 0ull;
    if (tid < BB) s->hdup[0][tid] = pack2(input[(size_t)(b0 + tid) * T_IN]);  // x(0)
    __syncthreads();

    float creg[4] = {0.f, 0.f, 0.f, 0.f};

    // ===== pipelined main loop: tick t -> L1@t, L2@t-1, L3@t-2 =====
    for (int t = 0; t < NTICK; t++) {
        ull   acc[8], hnew[4];
        float xr = 0.0f;
        const bool valid = gate_lane &&
            ((L == 0) ? (t <= T_IN - 1)
                      : (L == 1) ? (t >= 1 && t <= T_IN) : (t >= 2));
        if (gate_lane) {
            ulonglong2 bv = s->bq[L][j];
#pragma unroll
            for (int i = 0; i < 4; i++) { acc[i] = bv.x; acc[4 + i] = bv.y; }
            if (L == 0)      gloop<52>(s->W1q,  s->hdup,      j, bh4, acc);  // [x|h1]
            else if (L == 1) gloop<102>(s->W2q, s->hdup + 1,  j, bh4, acc);  // [h1|h2]
            else             gloop<102>(s->W3q, s->hdup + 52, j, bh4, acc);  // [h2|h3]
        } else if (head_lane && t >= 3) {
            int b = l - 102;
            out[(size_t)(b0 + b) * T_TOT + (t - 3)] = head_dot(s, b);
        } else if (xf_lane && t + 1 < T_IN) {
            xr = input[(size_t)(b0 + l - 102) * T_IN + t + 1];
        }
        if (valid) cell_local(acc, creg, hnew);
        __syncthreads();
        if (valid) hwrite(&s->hdup[1 + L * H + j][bh4], hnew);
        if (xf_lane && t + 1 < T_IN) s->hdup[0][l - 102] = pack2(xr);
        __syncthreads();
    }

    // ---- drain: out(511) + first autoregressive input ----
    if (tid < BB) {
        float v = head_dot(s, tid);
        out[(size_t)(b0 + tid) * T_TOT + (T_IN - 1)] = v;
        s->hdup[0][tid] = pack2(v);
    }
    __syncthreads();

    // ===== autoregressive future: layer-serial, thread-local cell =====
    for (int fs = 0; fs < T_FUT; fs++) {
#pragma unroll
        for (int lay = 0; lay < 3; lay++) {
            ull acc[8], hnew[4];
            const bool w = (L == lay) && gate_lane;
            if (w) {
                ulonglong2 bv = s->bq[lay][j];
#pragma unroll
                for (int i = 0; i < 4; i++) { acc[i] = bv.x; acc[4 + i] = bv.y; }
                if (lay == 0)      gloop<52>(s->W1q,  s->hdup,      j, bh4, acc);
                else if (lay == 1) gloop<102>(s->W2q, s->hdup + 1,  j, bh4, acc);
                else               gloop<102>(s->W3q, s->hdup + 52, j, bh4, acc);
                cell_local(acc, creg, hnew);
            }
            __syncthreads();
            if (w) hwrite(&s->hdup[1 + lay * H + j][bh4], hnew);
            __syncthreads();
        }
        if (tid < BB) {
            float v = head_dot(s, tid);
            out[(size_t)(b0 + tid) * T_TOT + T_IN + fs] = v;
            s->hdup[0][tid] = pack2(v);
        }
        __syncthreads();
    }
}

extern "C" void kernel_launch(void *const *d_in, const int *in_sizes, int n_in,
                              void *d_out, int out_size) {
    (void)in_sizes; (void)n_in; (void)out_size;
    cudaFuncSetAttribute(lstm_seq_kernel,
                         cudaFuncAttributeMaxDynamicSharedMemorySize,
                         (int)sizeof(Smem));
    lstm_seq_kernel<<<NCTA, TPB, sizeof(Smem)>>>(
        (const float *)d_in[0],
        (const float *)d_in[1], (const float *)d_in[2],
        (const float *)d_in[3], (const float *)d_in[4],
        (const float *)d_in[5], (const float *)d_in[6],
        (const float *)d_in[7], (const float *)d_in[8],
        (const float *)d_in[9], (const float *)d_in[10],
        (const float *)d_in[11], (const float *)d_in[12],
        (const float *)d_in[13], (const float *)d_in[14],
        (float *)d_out);
}